// round 2
// baseline (speedup 1.0000x reference)
#include <cuda_runtime.h>

#define NSEG   8
#define KPTS   768
#define NMAPS  7
#define NPTS   (NSEG * KPTS)       // 6144
#define EPM    (KPTS * KPTS)       // 589824 edges per map
#define ETOT   (NMAPS * EPM)       // 4128768 edges total

// Scratch: channel-interleaved PAF (m, y, x) -> (c0, c1), 56 MB
__device__ float2 g_paf[NMAPS * 1024 * 1024];
// Per-point endpoint PAF values: tabA[i] = PAF of map seg(i) at point i (x=0 sample, == p1)
//                                tabB[i] = PAF of map seg(i)-1 at point i (x=9 sample, == p2)
__device__ float2 g_tabA[NPTS];
__device__ float2 g_tabB[NPTS];

// Repack (m, c, y, x) -> (m, y, x, c) as float2; float4-vectorized: 4 pixels/thread.
__global__ void repack_kernel(const float* __restrict__ PAF) {
    int t = blockIdx.x * blockDim.x + threadIdx.x;      // one t per 4 pixels
    if (t >= NMAPS * (1048576 / 4)) return;
    int m    = t / (1048576 / 4);
    int pix4 = t - m * (1048576 / 4);                   // group of 4 pixels
    const float4* c0p = (const float4*)(PAF + ((size_t)(2 * m)     << 20));
    const float4* c1p = (const float4*)(PAF + ((size_t)(2 * m + 1) << 20));
    float4 c0 = __ldg(&c0p[pix4]);
    float4 c1 = __ldg(&c1p[pix4]);
    float2* dst = g_paf + ((size_t)m << 20) + (size_t)pix4 * 4;
    ((float4*)dst)[0] = make_float4(c0.x, c1.x, c0.y, c1.y);
    ((float4*)dst)[1] = make_float4(c0.z, c1.z, c0.w, c1.w);
}

__global__ void table_kernel(const int* __restrict__ sk, const float* __restrict__ PAF) {
    int i = blockIdx.x * blockDim.x + threadIdx.x;
    if (i >= NPTS) return;
    int s = i / KPTS;
    int x = sk[3 * i + 1];
    int y = sk[3 * i + 2];
    int pix = (y << 10) + x;                     // row = coord1, col = coord0
    float2 va = make_float2(0.f, 0.f);
    float2 vb = make_float2(0.f, 0.f);
    if (s < NMAPS) {                             // point used as p1 on map s
        va.x = PAF[((size_t)(2 * s)     << 20) + pix];
        va.y = PAF[((size_t)(2 * s + 1) << 20) + pix];
    }
    if (s >= 1) {                                // point used as p2 on map s-1
        int m = s - 1;
        vb.x = PAF[((size_t)(2 * m)     << 20) + pix];
        vb.y = PAF[((size_t)(2 * m + 1) << 20) + pix];
    }
    g_tabA[i] = va;
    g_tabB[i] = vb;
}

// One block per (map m, p2-index a); one thread per p1-index b.
__global__ __launch_bounds__(KPTS) void paf_main_kernel(const int* __restrict__ sk,
                                                        float* __restrict__ out) {
    int blk = blockIdx.x;
    int m = blk / KPTS;
    int a = blk - m * KPTS;
    int b = threadIdx.x;

    int i2 = (m + 1) * KPTS + a;     // p2 global point id
    int i1 = m * KPTS + b;           // p1 global point id

    int p2x = __ldg(&sk[3 * i2 + 1]);
    int p2y = __ldg(&sk[3 * i2 + 2]);
    int p1x = __ldg(&sk[3 * i1 + 1]);
    int p1y = __ldg(&sk[3 * i1 + 2]);

    int dx = p2x - p1x;
    int dy = p2y - p1y;
    float fdx = (float)dx, fdy = (float)dy;
    float R = sqrtf(fdx * fdx + fdy * fdy);

    float2 vA = g_tabA[i1];          // sample at x=0 (== p1)
    float2 vB = g_tabB[i2];          // sample at x=9 (== p2)

    const float2* paf = g_paf + ((size_t)m << 20);

    // Interior samples x=1..8: line = (p1*(9-x) + p2*x) // 9
    // n = p1*9 + d*x stays in [0, 9207]; floor(n/9) == (n*58255)>>19 exactly there.
    float2 v[8];
    int nx = p1x * 9, ny = p1y * 9;
#pragma unroll
    for (int s = 0; s < 8; s++) {
        nx += dx; ny += dy;
        int lx = (nx * 58255) >> 19;
        int ly = (ny * 58255) >> 19;
        v[s] = __ldg(&paf[(ly << 10) + lx]);
    }

    float sx = vA.x + vB.x;
    float sy = vA.y + vB.y;
#pragma unroll
    for (int s = 0; s < 8; s++) { sx += v[s].x; sy += v[s].y; }

    float acc = fdx * sx + fdy * sy;
    float li = (R > 0.f) ? (acc / (10.f * R)) : 0.f;   // NaN (R==0) -> 0

    int idx = m * EPM + a * KPTS + b;
    // Output layout (float32): rows [i1 | i2 | li | R], each ETOT long
    out[idx]            = (float)i1;
    out[ETOT + idx]     = (float)i2;
    out[2 * ETOT + idx] = li;
    out[3 * ETOT + idx] = R;
}

extern "C" void kernel_launch(void* const* d_in, const int* in_sizes, int n_in,
                              void* d_out, int out_size) {
    const int*   sk  = (const int*)d_in[0];     // skeletons: (6144, 3) int32 [seg, x, y]
    const float* PAF = (const float*)d_in[1];   // (7, 2, 1024, 1024) float32
    float* out = (float*)d_out;

    repack_kernel<<<(NMAPS * (1048576 / 4) + 255) / 256, 256>>>(PAF);
    table_kernel<<<(NPTS + 255) / 256, 256>>>(sk, PAF);
    paf_main_kernel<<<NMAPS * KPTS, KPTS>>>(sk, out);
}